// round 13
// baseline (speedup 1.0000x reference)
#include <cuda_runtime.h>
#include <math.h>

#define NCTA 64
#define NTHREADS 1024
#define BB 256            // batch
#define SS 2048           // sequence
#define NIN 128
#define HH 256
#define NOUT 128
#define NG 8              // k-groups
#define KPG 32            // k per group

typedef unsigned long long ull;

// Persistent device state
__device__ __align__(16) float g_P[(size_t)SS * HH * BB];   // [t][j][b]
__device__ __align__(16) float g_h[2][HH * BB];             // [k][b], double buffered
__device__ unsigned g_ctr;                                  // monotonic arrival counter

__device__ __forceinline__ float gelu_exact(float x) {
    return 0.5f * x * (1.0f + erff(x * 0.70710678118654752f));
}

// packed fp32x2 ops (sm_103a)
#define FMA2(acc, a, w) asm("fma.rn.f32x2 %0, %1, %2, %0;" : "+l"(acc) : "l"(a), "l"(w))
#define ADD2_(d, a, b)  asm("add.rn.f32x2 %0, %1, %2;"     : "=l"(d)  : "l"(a), "l"(b))
#define BARSYNC(id, n)  asm volatile("bar.sync %0, %1;" :: "r"(id), "r"(n) : "memory")

// ================= Precompute P[t][j][b] = sum_k X[b][t][k] * W_ih[j][k] + b_ih[j] =================
#define PCS 68
__global__ void __launch_bounds__(256, 1) precompute_P_kernel(
    const float* __restrict__ X, const float* __restrict__ W_ih,
    const float* __restrict__ b_ih)
{
    extern __shared__ float ps[];
    float* Ws = ps;
    float* Xs = ps + 128 * PCS;

    const int tid = threadIdx.x;
    const int b0 = blockIdx.x * 64;
    const int j0 = blockIdx.y * 64;
    const int t  = blockIdx.z;

    for (int e = tid; e < 64 * 128; e += 256) {
        int j = e >> 7, k = e & 127;
        Ws[k * PCS + j] = W_ih[(size_t)(j0 + j) * (NIN + HH) + k];
    }
    for (int e = tid; e < 64 * 128; e += 256) {
        int b = e >> 7, k = e & 127;
        Xs[k * PCS + b] = X[((size_t)(b0 + b) * SS + t) * NIN + k];
    }
    __syncthreads();

    const int tx = tid & 15;
    const int ty = tid >> 4;
    float acc[4][4];
    #pragma unroll
    for (int i = 0; i < 4; ++i)
        #pragma unroll
        for (int jj = 0; jj < 4; ++jj) acc[jj][i] = 0.f;

    #pragma unroll 8
    for (int k = 0; k < 128; ++k) {
        float4 wv = *(const float4*)&Ws[k * PCS + ty * 4];
        float4 xv = *(const float4*)&Xs[k * PCS + tx * 4];
        acc[0][0] = fmaf(wv.x, xv.x, acc[0][0]);
        acc[0][1] = fmaf(wv.x, xv.y, acc[0][1]);
        acc[0][2] = fmaf(wv.x, xv.z, acc[0][2]);
        acc[0][3] = fmaf(wv.x, xv.w, acc[0][3]);
        acc[1][0] = fmaf(wv.y, xv.x, acc[1][0]);
        acc[1][1] = fmaf(wv.y, xv.y, acc[1][1]);
        acc[1][2] = fmaf(wv.y, xv.z, acc[1][2]);
        acc[1][3] = fmaf(wv.y, xv.w, acc[1][3]);
        acc[2][0] = fmaf(wv.z, xv.x, acc[2][0]);
        acc[2][1] = fmaf(wv.z, xv.y, acc[2][1]);
        acc[2][2] = fmaf(wv.z, xv.z, acc[2][2]);
        acc[2][3] = fmaf(wv.z, xv.w, acc[2][3]);
        acc[3][0] = fmaf(wv.w, xv.x, acc[3][0]);
        acc[3][1] = fmaf(wv.w, xv.y, acc[3][1]);
        acc[3][2] = fmaf(wv.w, xv.z, acc[3][2]);
        acc[3][3] = fmaf(wv.w, xv.w, acc[3][3]);
    }

    #pragma unroll
    for (int jj = 0; jj < 4; ++jj) {
        int j = j0 + ty * 4 + jj;
        float bj = b_ih[j];
        float4 r = make_float4(acc[jj][0] + bj, acc[jj][1] + bj,
                               acc[jj][2] + bj, acc[jj][3] + bj);
        *(float4*)&g_P[((size_t)t * HH + j) * BB + b0 + tx * 4] = r;
    }
}

// ================= main persistent kernel =================
// 64 CTAs x 1024 threads = 8 k-groups x 128; thread (g, gt) owns batch pair
// {2gt, 2gt+1}, k in [32g, 32g+32). CTA c owns z-columns j0=4c..4c+3 and
// out-columns n0=2c, 2c+1. Packed f32x2 math. Barrier: monotonic counter,
// red.release arrival (after groups 0-3's h stores), tid0 acquire-spin.
__global__ void __launch_bounds__(NTHREADS, 1) rec_kernel(
    const float* __restrict__ W_ih, const float* __restrict__ W_ho,
    const float* __restrict__ b_ho,
    const float* __restrict__ gamma, const float* __restrict__ beta,
    float* __restrict__ out)
{
    __shared__ __align__(16) ull sPZ[4][NG * 128];  // partials per z column
    __shared__ __align__(16) ull sPO[2][NG * 128];  // partials per out column
    __shared__ __align__(16) ull sWz[4][HH];        // {w,w} dup pairs, z columns
    __shared__ __align__(16) ull sWo[2][HH];        // {w,w} dup pairs, out columns
    __shared__ float sred[4][4][2];                 // [z-col group][warp][s,q]
    __shared__ unsigned s_base;

    const int tid  = threadIdx.x;
    const int lane = tid & 31;
    const int g    = tid >> 7;      // k-group 0..7
    const int gt   = tid & 127;     // thread-in-group; owns b = 2gt, 2gt+1
    const int wg   = gt >> 5;       // warp within group
    const int c    = blockIdx.x;
    const int j0   = 4 * c;         // 4 z columns
    const int n0   = 2 * c;         // 2 out columns
    const int k0g  = g * KPG;

    // duplicated weight pairs {w,w}
    for (int k = tid; k < HH; k += NTHREADS) {
        #pragma unroll
        for (int q = 0; q < 4; ++q) {
            unsigned w = __float_as_uint(W_ih[(size_t)(j0 + q) * (NIN + HH) + NIN + k]);
            sWz[q][k] = ((ull)w << 32) | w;
        }
        #pragma unroll
        for (int q = 0; q < 2; ++q) {
            unsigned w = __float_as_uint(W_ho[(size_t)(n0 + q) * HH + k]);
            sWo[q][k] = ((ull)w << 32) | w;
        }
    }

    const float ga  = gamma[j0 + (g & 3)];   // used by groups 0-3
    const float be  = beta[j0 + (g & 3)];
    const float bho = b_ho[n0 + (g & 1)];    // used by groups 4-5

    if (tid == 0) {
        unsigned v;
        asm volatile("ld.acquire.gpu.global.b32 %0, [%1];" : "=r"(v) : "l"(&g_ctr));
        s_base = v;
    }
    __syncthreads();
    const unsigned base = s_base;

    ull pPu = 0;
    if (g < 4)
        pPu = __ldg((const ull*)g_P + (size_t)(j0 + g) * 128 + gt);

    for (int t = 0; t <= SS; ++t) {
        const ull* __restrict__ hrow = (const ull*)(g_h[t & 1]);   // h_{t-1}, [256][128] pairs

        // ===== partial GEMMs over this group's 32 k (packed f32x2, 6 accs) =====
        ull z0 = 0ull, z1 = 0ull, z2 = 0ull, z3 = 0ull, o0 = 0ull, o1 = 0ull;
        #pragma unroll
        for (int kc = 0; kc < KPG; kc += 4) {
            ull a0 = __ldcg(hrow + (size_t)(k0g + kc + 0) * 128 + gt);
            ull a1 = __ldcg(hrow + (size_t)(k0g + kc + 1) * 128 + gt);
            ull a2 = __ldcg(hrow + (size_t)(k0g + kc + 2) * 128 + gt);
            ull a3 = __ldcg(hrow + (size_t)(k0g + kc + 3) * 128 + gt);
            #pragma unroll
            for (int i = 0; i < 4; i += 2) {
                const int k = k0g + kc + i;
                ull ax = (i == 0) ? a0 : a2;
                ull ay = (i == 0) ? a1 : a3;
                ulonglong2 wz0 = *(const ulonglong2*)&sWz[0][k];
                ulonglong2 wz1 = *(const ulonglong2*)&sWz[1][k];
                ulonglong2 wz2 = *(const ulonglong2*)&sWz[2][k];
                ulonglong2 wz3 = *(const ulonglong2*)&sWz[3][k];
                ulonglong2 wo0 = *(const ulonglong2*)&sWo[0][k];
                ulonglong2 wo1 = *(const ulonglong2*)&sWo[1][k];
                FMA2(z0, ax, wz0.x); FMA2(z0, ay, wz0.y);
                FMA2(z1, ax, wz1.x); FMA2(z1, ay, wz1.y);
                FMA2(z2, ax, wz2.x); FMA2(z2, ay, wz2.y);
                FMA2(z3, ax, wz3.x); FMA2(z3, ay, wz3.y);
                FMA2(o0, ax, wo0.x); FMA2(o0, ay, wo0.y);
                FMA2(o1, ax, wo1.x); FMA2(o1, ay, wo1.y);
            }
        }
        const int pb = (g << 7) + gt;
        sPZ[0][pb] = z0; sPZ[1][pb] = z1; sPZ[2][pb] = z2; sPZ[3][pb] = z3;
        sPO[0][pb] = o0; sPO[1][pb] = o1;
        __syncthreads();   // S1: partials visible; all threads done reading h_{t-1}

        // ===== groups 4/5: out column n0+(g-4) for step t-1 =====
        if ((g == 4 || g == 5) && t > 0) {
            const ull* sp = sPO[g - 4] + gt;
            ull a01, a23, a45, a67, b03, b47, O;
            ADD2_(a01, sp[0],   sp[128]); ADD2_(a23, sp[256], sp[384]);
            ADD2_(a45, sp[512], sp[640]); ADD2_(a67, sp[768], sp[896]);
            ADD2_(b03, a01, a23); ADD2_(b47, a45, a67);
            ADD2_(O, b03, b47);
            float2 of = *(float2*)&O;
            const int nn = n0 + (g - 4);
            out[((size_t)(2 * gt)     * SS + (t - 1)) * NOUT + nn] = gelu_exact(of.x + bho);
            out[((size_t)(2 * gt + 1) * SS + (t - 1)) * NOUT + nn] = gelu_exact(of.y + bho);
        }
        if (t == SS) break;

        // ===== groups 0-3: merge own z column + BN + GELU + h store + arrival =====
        if (g < 4) {
            const ull* sp = sPZ[g] + gt;
            ull a01, a23, a45, a67, b03, b47, s8, Zm;
            ADD2_(a01, sp[0],   sp[128]); ADD2_(a23, sp[256], sp[384]);
            ADD2_(a45, sp[512], sp[640]); ADD2_(a67, sp[768], sp[896]);
            ADD2_(b03, a01, a23); ADD2_(b47, a45, a67);
            ADD2_(s8, b03, b47);
            ADD2_(Zm, s8, pPu);
            float2 zf = *(float2*)&Zm;
            float zl = zf.x, zh = zf.y;

            float s = zl + zh;
            float q = fmaf(zl, zl, zh * zh);
            #pragma unroll
            for (int o = 16; o > 0; o >>= 1) {
                s += __shfl_down_sync(0xffffffffu, s, o);
                q += __shfl_down_sync(0xffffffffu, q, o);
            }
            if (lane == 0) { sred[g][wg][0] = s; sred[g][wg][1] = q; }
            BARSYNC(4 + g, 128);                       // group-scoped reduce (ids 4..7)
            float S = sred[g][0][0] + sred[g][1][0] + sred[g][2][0] + sred[g][3][0];
            float Q = sred[g][0][1] + sred[g][1][1] + sred[g][2][1] + sred[g][3][1];
            float mu  = S * (1.0f / BB);
            float var = Q * (1.0f / BB) - mu * mu;     // biased
            float rs  = rsqrtf(var + 1e-5f);
            float h0 = gelu_exact((zl - mu) * rs * ga + be);
            float h1 = gelu_exact((zh - mu) * rs * ga + be);
            ((float2*)g_h[(t & 1) ^ 1])[(size_t)(j0 + g) * 128 + gt] = make_float2(h0, h1);

            BARSYNC(1, 512);                           // groups 0-3: h stores issued
            if (tid == 0)                              // arrival (release orders h stores)
                asm volatile("red.release.gpu.global.add.u32 [%0], %1;"
                             :: "l"(&g_ctr), "r"(1u) : "memory");
            if (t + 1 < SS)                            // prefetch next P off the path
                pPu = __ldg((const ull*)g_P + ((size_t)(t + 1) * HH + j0 + g) * 128 + gt);
        }

        // ===== wait: all 64 CTAs arrived for step t =====
        if (tid == 0) {
            const unsigned target = base + (unsigned)(t + 1) * NCTA;
            unsigned v;
            do {
                asm volatile("ld.acquire.gpu.global.b32 %0, [%1];"
                             : "=r"(v) : "l"(&g_ctr) : "memory");
            } while ((int)(v - target) < 0);
        }
        __syncthreads();   // S4: barrier passed; safe to read h_t and overwrite partials
    }
}

// ---------------- launch ----------------
extern "C" void kernel_launch(void* const* d_in, const int* in_sizes, int n_in,
                              void* d_out, int out_size) {
    const float* X     = (const float*)d_in[0];
    const float* W_ih  = (const float*)d_in[1];
    const float* b_ih  = (const float*)d_in[2];
    const float* W_ho  = (const float*)d_in[3];
    const float* b_ho  = (const float*)d_in[4];
    const float* gamma = (const float*)d_in[5];
    const float* beta  = (const float*)d_in[6];
    float* out = (float*)d_out;

    // zero h buffer 0 (h_{-1} = 0)
    void* hptr = nullptr;
    cudaGetSymbolAddress(&hptr, g_h);
    cudaMemsetAsync(hptr, 0, sizeof(float) * HH * BB, 0);

    // precompute P = X @ Wx.T + b_ih
    {
        size_t psmem = 2u * 128 * PCS * sizeof(float);
        cudaFuncSetAttribute(precompute_P_kernel,
                             cudaFuncAttributeMaxDynamicSharedMemorySize, (int)psmem);
        dim3 pgrid(4, 4, SS);
        precompute_P_kernel<<<pgrid, 256, psmem>>>(X, W_ih, b_ih);
    }

    // persistent recurrence kernel (static smem only)
    rec_kernel<<<NCTA, NTHREADS>>>(W_ih, W_ho, b_ho, gamma, beta, out);
}

// round 15
// speedup vs baseline: 1.1536x; 1.1536x over previous
#include <cuda_runtime.h>
#include <math.h>

#define NCTA 128
#define NTHREADS 1024
#define BB 256            // batch
#define SS 2048           // sequence
#define NIN 128
#define HH 256
#define NOUT 128
#define NG 8              // k-groups
#define KPG 32            // k per group
#define FSTRIDE 32        // flag padding: 32 ints = 128B per CTA

typedef unsigned long long ull;

// Persistent device state
__device__ __align__(16) float g_P[(size_t)SS * HH * BB];   // [t][j][b]
__device__ __align__(16) float g_h[2][HH * BB];             // [k][b], double buffered
__device__ int g_flags[NCTA * FSTRIDE];                     // per-CTA step flags, 128B apart

__device__ __forceinline__ float gelu_exact(float x) {
    return 0.5f * x * (1.0f + erff(x * 0.70710678118654752f));
}

// packed fp32x2 ops (sm_103a)
#define FMA2(acc, a, w) asm("fma.rn.f32x2 %0, %1, %2, %0;" : "+l"(acc) : "l"(a), "l"(w))
#define ADD2_(d, a, b)  asm("add.rn.f32x2 %0, %1, %2;"     : "=l"(d)  : "l"(a), "l"(b))
#define BARSYNC(id, n)  asm volatile("bar.sync %0, %1;" :: "r"(id), "r"(n) : "memory")

// ================= Precompute P[t][j][b] = sum_k X[b][t][k] * W_ih[j][k] + b_ih[j] =================
#define PCS 68
__global__ void __launch_bounds__(256, 1) precompute_P_kernel(
    const float* __restrict__ X, const float* __restrict__ W_ih,
    const float* __restrict__ b_ih)
{
    extern __shared__ float ps[];
    float* Ws = ps;
    float* Xs = ps + 128 * PCS;

    const int tid = threadIdx.x;
    const int b0 = blockIdx.x * 64;
    const int j0 = blockIdx.y * 64;
    const int t  = blockIdx.z;

    for (int e = tid; e < 64 * 128; e += 256) {
        int j = e >> 7, k = e & 127;
        Ws[k * PCS + j] = W_ih[(size_t)(j0 + j) * (NIN + HH) + k];
    }
    for (int e = tid; e < 64 * 128; e += 256) {
        int b = e >> 7, k = e & 127;
        Xs[k * PCS + b] = X[((size_t)(b0 + b) * SS + t) * NIN + k];
    }
    __syncthreads();

    const int tx = tid & 15;
    const int ty = tid >> 4;
    float acc[4][4];
    #pragma unroll
    for (int i = 0; i < 4; ++i)
        #pragma unroll
        for (int jj = 0; jj < 4; ++jj) acc[jj][i] = 0.f;

    #pragma unroll 8
    for (int k = 0; k < 128; ++k) {
        float4 wv = *(const float4*)&Ws[k * PCS + ty * 4];
        float4 xv = *(const float4*)&Xs[k * PCS + tx * 4];
        acc[0][0] = fmaf(wv.x, xv.x, acc[0][0]);
        acc[0][1] = fmaf(wv.x, xv.y, acc[0][1]);
        acc[0][2] = fmaf(wv.x, xv.z, acc[0][2]);
        acc[0][3] = fmaf(wv.x, xv.w, acc[0][3]);
        acc[1][0] = fmaf(wv.y, xv.x, acc[1][0]);
        acc[1][1] = fmaf(wv.y, xv.y, acc[1][1]);
        acc[1][2] = fmaf(wv.y, xv.z, acc[1][2]);
        acc[1][3] = fmaf(wv.y, xv.w, acc[1][3]);
        acc[2][0] = fmaf(wv.z, xv.x, acc[2][0]);
        acc[2][1] = fmaf(wv.z, xv.y, acc[2][1]);
        acc[2][2] = fmaf(wv.z, xv.z, acc[2][2]);
        acc[2][3] = fmaf(wv.z, xv.w, acc[2][3]);
        acc[3][0] = fmaf(wv.w, xv.x, acc[3][0]);
        acc[3][1] = fmaf(wv.w, xv.y, acc[3][1]);
        acc[3][2] = fmaf(wv.w, xv.z, acc[3][2]);
        acc[3][3] = fmaf(wv.w, xv.w, acc[3][3]);
    }

    #pragma unroll
    for (int jj = 0; jj < 4; ++jj) {
        int j = j0 + ty * 4 + jj;
        float bj = b_ih[j];
        float4 r = make_float4(acc[jj][0] + bj, acc[jj][1] + bj,
                               acc[jj][2] + bj, acc[jj][3] + bj);
        *(float4*)&g_P[((size_t)t * HH + j) * BB + b0 + tx * 4] = r;
    }
}

// ================= main persistent kernel =================
// 128 CTAs x 1024 threads = 8 k-groups x 128; thread (g, gt) owns batch pair
// {2gt, 2gt+1}, k in [32g, 32g+32), packed f32x2 math. CTA c owns z-columns
// j0=2c,2c+1 and out-column n0=c. Barrier: per-CTA release-flag stores to
// DISTINCT 128B lines (no L2 atomic serialization); ONE warp per CTA polls
// all 128 flags (4 LDG.32 per lane per round).
__global__ void __launch_bounds__(NTHREADS, 1) rec_kernel(
    const float* __restrict__ W_ih, const float* __restrict__ W_ho,
    const float* __restrict__ b_ho,
    const float* __restrict__ gamma, const float* __restrict__ beta,
    float* __restrict__ out)
{
    __shared__ __align__(16) ull sPZ0[NG * 128];   // per-group partials
    __shared__ __align__(16) ull sPZ1[NG * 128];
    __shared__ __align__(16) ull sPO [NG * 128];
    __shared__ __align__(16) ull sW0d[HH];         // {w,w} duplicated pairs
    __shared__ __align__(16) ull sW1d[HH];
    __shared__ __align__(16) ull sWod[HH];
    __shared__ float sred[2][4][2];                // [group 0/1][warp][s,q]
    __shared__ int s_base;

    const int tid  = threadIdx.x;
    const int lane = tid & 31;
    const int g    = tid >> 7;      // k-group 0..7
    const int gt   = tid & 127;     // thread-in-group; owns b = 2gt, 2gt+1
    const int wg   = gt >> 5;       // warp within group
    const int c    = blockIdx.x;
    const int j0   = 2 * c;
    const int n0   = c;
    const int k0g  = g * KPG;

    // duplicated weight pairs {w,w}
    for (int k = tid; k < HH; k += NTHREADS) {
        unsigned w0 = __float_as_uint(W_ih[(size_t)j0 * (NIN + HH) + NIN + k]);
        unsigned w1 = __float_as_uint(W_ih[(size_t)(j0 + 1) * (NIN + HH) + NIN + k]);
        unsigned wo = __float_as_uint(W_ho[(size_t)n0 * HH + k]);
        sW0d[k] = ((ull)w0 << 32) | w0;
        sW1d[k] = ((ull)w1 << 32) | w1;
        sWod[k] = ((ull)wo << 32) | wo;
    }

    const float ga  = gamma[j0 + (g & 1)];
    const float be  = beta[j0 + (g & 1)];
    const float bho = b_ho[n0];

    if (tid == 0) {
        int v;
        asm volatile("ld.acquire.gpu.global.b32 %0, [%1];"
                     : "=r"(v) : "l"(&g_flags[c * FSTRIDE]));
        s_base = v;                  // all flags equal at launch (monotonic)
    }
    __syncthreads();
    const int base = s_base;

    // poll pointers: warp 0 covers all 128 flags, 4 per lane
    const int* fp0 = &g_flags[(lane +  0) * FSTRIDE];
    const int* fp1 = &g_flags[(lane + 32) * FSTRIDE];
    const int* fp2 = &g_flags[(lane + 64) * FSTRIDE];
    const int* fp3 = &g_flags[(lane + 96) * FSTRIDE];

    ull pPu = 0;
    if (g < 2)
        pPu = __ldg((const ull*)g_P + (size_t)(j0 + g) * 128 + gt);

    for (int t = 0; t <= SS; ++t) {
        const ull* __restrict__ hrow = (const ull*)(g_h[t & 1]);   // h_{t-1}, [256][128] pairs

        // ===== partial GEMMs over this group's 32 k (packed f32x2) =====
        ull z0 = 0ull, z1 = 0ull, oa = 0ull;
        #pragma unroll
        for (int kc = 0; kc < KPG; kc += 8) {
            ull a[8];
            #pragma unroll
            for (int i = 0; i < 8; ++i)
                a[i] = __ldcg(hrow + (size_t)(k0g + kc + i) * 128 + gt);
            #pragma unroll
            for (int i = 0; i < 8; i += 2) {
                const int k = k0g + kc + i;
                ulonglong2 w0 = *(const ulonglong2*)&sW0d[k];
                ulonglong2 w1 = *(const ulonglong2*)&sW1d[k];
                ulonglong2 wo = *(const ulonglong2*)&sWod[k];
                FMA2(z0, a[i],     w0.x);
                FMA2(z1, a[i],     w1.x);
                FMA2(oa, a[i],     wo.x);
                FMA2(z0, a[i + 1], w0.y);
                FMA2(z1, a[i + 1], w1.y);
                FMA2(oa, a[i + 1], wo.y);
            }
        }
        const int pb = (g << 7) + gt;
        sPZ0[pb] = z0;
        sPZ1[pb] = z1;
        sPO [pb] = oa;
        __syncthreads();   // S1: partials visible; all threads done reading h_{t-1}

        // ===== group 2: o_{t-1} (off the release path, overlaps the spin) =====
        if (g == 2 && t > 0) {
            const ull* sp = sPO + gt;
            ull a01, a23, a45, a67, b03, b47, O;
            ADD2_(a01, sp[0],   sp[128]); ADD2_(a23, sp[256], sp[384]);
            ADD2_(a45, sp[512], sp[640]); ADD2_(a67, sp[768], sp[896]);
            ADD2_(b03, a01, a23); ADD2_(b47, a45, a67);
            ADD2_(O, b03, b47);
            float2 of = *(float2*)&O;
            out[((size_t)(2 * gt)     * SS + (t - 1)) * NOUT + n0] = gelu_exact(of.x + bho);
            out[((size_t)(2 * gt + 1) * SS + (t - 1)) * NOUT + n0] = gelu_exact(of.y + bho);
        }
        if (t == SS) break;

        // ===== groups 0/1: merge own z column + BN + GELU + h store + flag =====
        if (g < 2) {
            const ull* sp = ((g == 0) ? sPZ0 : sPZ1) + gt;
            ull a01, a23, a45, a67, b03, b47, s8, Zm;
            ADD2_(a01, sp[0],   sp[128]); ADD2_(a23, sp[256], sp[384]);
            ADD2_(a45, sp[512], sp[640]); ADD2_(a67, sp[768], sp[896]);
            ADD2_(b03, a01, a23); ADD2_(b47, a45, a67);
            ADD2_(s8, b03, b47);
            ADD2_(Zm, s8, pPu);
            float2 zf = *(float2*)&Zm;
            float zl = zf.x, zh = zf.y;

            float s = zl + zh;
            float q = fmaf(zl, zl, zh * zh);
            #pragma unroll
            for (int o = 16; o > 0; o >>= 1) {
                s += __shfl_down_sync(0xffffffffu, s, o);
                q += __shfl_down_sync(0xffffffffu, q, o);
            }
            if (lane == 0) { sred[g][wg][0] = s; sred[g][wg][1] = q; }
            BARSYNC(1 + g, 128);                       // group-scoped reduce
            float S = sred[g][0][0] + sred[g][1][0] + sred[g][2][0] + sred[g][3][0];
            float Q = sred[g][0][1] + sred[g][1][1] + sred[g][2][1] + sred[g][3][1];
            float mu  = S * (1.0f / BB);
            float var = Q * (1.0f / BB) - mu * mu;     // biased
            float rs  = rsqrtf(var + 1e-5f);
            float h0 = gelu_exact((zl - mu) * rs * ga + be);
            float h1 = gelu_exact((zh - mu) * rs * ga + be);
            ((float2*)g_h[(t & 1) ^ 1])[(size_t)(j0 + g) * 128 + gt] = make_float2(h0, h1);

            BARSYNC(3, 256);                           // groups 0+1: h stores issued
            if (tid == 0)                              // release-flag (orders h stores);
                asm volatile("st.release.gpu.global.b32 [%0], %1;"
                             :: "l"(&g_flags[c * FSTRIDE]), "r"(base + t + 1) : "memory");
            if (t + 1 < SS)                            // prefetch next P off the path
                pPu = __ldg((const ull*)g_P + ((size_t)(t + 1) * HH + j0 + g) * 128 + gt);
        }

        // ===== wait: all 128 CTAs' flags reached t+1 (warp 0 polls) =====
        if (tid < 32) {
            const int target = base + t + 1;
            int done;
            do {
                int v0, v1, v2, v3;
                asm volatile("ld.acquire.gpu.global.b32 %0, [%1];" : "=r"(v0) : "l"(fp0) : "memory");
                asm volatile("ld.acquire.gpu.global.b32 %0, [%1];" : "=r"(v1) : "l"(fp1) : "memory");
                asm volatile("ld.acquire.gpu.global.b32 %0, [%1];" : "=r"(v2) : "l"(fp2) : "memory");
                asm volatile("ld.acquire.gpu.global.b32 %0, [%1];" : "=r"(v3) : "l"(fp3) : "memory");
                done = __all_sync(0xffffffffu,
                                  (v0 - target) >= 0 && (v1 - target) >= 0 &&
                                  (v2 - target) >= 0 && (v3 - target) >= 0);
            } while (!done);
        }
        __syncthreads();   // S4: barrier passed; safe to read h_t and overwrite partials
    }
}

// ---------------- launch ----------------
extern "C" void kernel_launch(void* const* d_in, const int* in_sizes, int n_in,
                              void* d_out, int out_size) {
    const float* X     = (const float*)d_in[0];
    const float* W_ih  = (const float*)d_in[1];
    const float* b_ih  = (const float*)d_in[2];
    const float* W_ho  = (const float*)d_in[3];
    const float* b_ho  = (const float*)d_in[4];
    const float* gamma = (const float*)d_in[5];
    const float* beta  = (const float*)d_in[6];
    float* out = (float*)d_out;

    // zero h buffer 0 (h_{-1} = 0)
    void* hptr = nullptr;
    cudaGetSymbolAddress(&hptr, g_h);
    cudaMemsetAsync(hptr, 0, sizeof(float) * HH * BB, 0);

    // precompute P = X @ Wx.T + b_ih
    {
        size_t psmem = 2u * 128 * PCS * sizeof(float);
        cudaFuncSetAttribute(precompute_P_kernel,
                             cudaFuncAttributeMaxDynamicSharedMemorySize, (int)psmem);
        dim3 pgrid(4, 4, SS);
        precompute_P_kernel<<<pgrid, 256, psmem>>>(X, W_ih, b_ih);
    }

    // persistent recurrence kernel (static smem only)
    rec_kernel<<<NCTA, NTHREADS>>>(W_ih, W_ho, b_ho, gamma, beta, out);
}